// round 1
// baseline (speedup 1.0000x reference)
#include <cuda_runtime.h>

#define Bb   64
#define Tt   128
#define Ee   256
#define Hh   512
#define G4H  2048
#define NEo  32
#define GSZ  (Tt*Bb*G4H)   /* 16,777,216 floats per gate buffer */

typedef unsigned long long u64;

// ---------------- scratch (__device__ globals: allocation-free) ----------------
__device__ float g_x0[Tt*Bb*Ee];                 // embedded inputs  [T*B, E]   (8 MB)
__device__ float g_x1[Tt*Bb*2*Hh];               // layer-0 outputs  [T*B, 2H]  (32 MB)
__device__ float g_G[(size_t)4*GSZ];             // gate pre-acts: G0f,G0b,G1f,G1b (256 MB)
__device__ float g_hbuf[4][2][Bb*Hh];            // h ping-pong per sequence
__device__ float g_cbuf[4][Bb*Hh];               // c state per sequence

// ---------------- packed f32x2 helpers ----------------
__device__ __forceinline__ void fma2(u64 &c, u64 a, u64 b) {
    asm("fma.rn.f32x2 %0, %1, %2, %0;" : "+l"(c) : "l"(a), "l"(b));
}
__device__ __forceinline__ float2 unpack2(u64 v) {
    float2 r; asm("mov.b64 {%0,%1}, %2;" : "=f"(r.x), "=f"(r.y) : "l"(v)); return r;
}
__device__ __forceinline__ float sigm(float x) { return 1.f / (1.f + __expf(-x)); }

// ---------------- init: zero h (parity 0 + 1) and c ----------------
__global__ void init_states() {
    int i = blockIdx.x * blockDim.x + threadIdx.x;
    if (i < 4*2*Bb*Hh) ((float*)g_hbuf)[i] = 0.f;
    if (i < 4*Bb*Hh)   ((float*)g_cbuf)[i] = 0.f;
}

// ---------------- embedding gather: g_x0[t*B+b][k] = emb[q[b][t]][k] ----------------
__global__ void gather_embed(const int* __restrict__ q, const float* __restrict__ emb) {
    int r = blockIdx.x;              // r = t*B + b
    int b = r & (Bb - 1);
    int t = r >> 6;
    int qi = q[b * Tt + t];
    const float4* src = (const float4*)(emb + (size_t)qi * Ee);
    float4* dst = (float4*)(g_x0 + (size_t)r * Ee);
    dst[threadIdx.x] = src[threadIdx.x];
}

// ---------------- feedforward GEMM: C = A[8192,K] @ W[2048,K]^T + b1 + b2 ----------------
// 128x128 tile, BK=8, 256 threads, 8x8 per-thread microtile with packed f32x2 FMA.
// A is stored DUPLICATED in smem so (a,a) pairs are direct LDS.128 reads.
__global__ __launch_bounds__(256) void sgemm_ff(int asel, int gsel, int K,
        const float* __restrict__ W,
        const float* __restrict__ b1, const float* __restrict__ b2)
{
    const float* __restrict__ A = asel ? g_x1 : g_x0;
    float* __restrict__ C = g_G + (size_t)gsel * GSZ;

    __shared__ __align__(16) float As[8][256];   // duplicated A: As[k][2m],As[k][2m+1]
    __shared__ __align__(16) float Bs[8][128];

    int tid = threadIdx.x;
    int m0 = blockIdx.y * 128;
    int n0 = blockIdx.x * 128;
    int ty = tid >> 4, tx = tid & 15;
    int mloc = ty * 8, nloc = tx * 8;

    u64 acc[8][4];
#pragma unroll
    for (int r = 0; r < 8; r++)
#pragma unroll
        for (int c = 0; c < 4; c++) acc[r][c] = 0ull;

    int lrow = tid >> 1;
    int lk = (tid & 1) * 4;
    const float* Ap = A + (size_t)(m0 + lrow) * K + lk;
    const float* Wp = W + (size_t)(n0 + lrow) * K + lk;

    for (int k0 = 0; k0 < K; k0 += 8) {
        float4 av = *(const float4*)(Ap + k0);
        float4 wv = *(const float4*)(Wp + k0);
        __syncthreads();
        As[lk+0][2*lrow] = av.x; As[lk+0][2*lrow+1] = av.x;
        As[lk+1][2*lrow] = av.y; As[lk+1][2*lrow+1] = av.y;
        As[lk+2][2*lrow] = av.z; As[lk+2][2*lrow+1] = av.z;
        As[lk+3][2*lrow] = av.w; As[lk+3][2*lrow+1] = av.w;
        Bs[lk+0][lrow] = wv.x;
        Bs[lk+1][lrow] = wv.y;
        Bs[lk+2][lrow] = wv.z;
        Bs[lk+3][lrow] = wv.w;
        __syncthreads();
#pragma unroll
        for (int k = 0; k < 8; k++) {
            ulonglong2 a0 = *(const ulonglong2*)&As[k][2*mloc];
            ulonglong2 a1 = *(const ulonglong2*)&As[k][2*mloc+4];
            ulonglong2 a2 = *(const ulonglong2*)&As[k][2*mloc+8];
            ulonglong2 a3 = *(const ulonglong2*)&As[k][2*mloc+12];
            ulonglong2 q0 = *(const ulonglong2*)&Bs[k][nloc];
            ulonglong2 q1 = *(const ulonglong2*)&Bs[k][nloc+4];
            u64 ar[8] = {a0.x,a0.y,a1.x,a1.y,a2.x,a2.y,a3.x,a3.y};
            u64 br[4] = {q0.x,q0.y,q1.x,q1.y};
#pragma unroll
            for (int r = 0; r < 8; r++)
#pragma unroll
                for (int c = 0; c < 4; c++)
                    fma2(acc[r][c], ar[r], br[c]);
        }
    }

#pragma unroll
    for (int r = 0; r < 8; r++) {
        int gm = m0 + mloc + r;
        float* crow = C + (size_t)gm * G4H + n0 + nloc;
#pragma unroll
        for (int c = 0; c < 4; c++) {
            float2 v = unpack2(acc[r][c]);
            int gn = n0 + nloc + c * 2;
            crow[c*2]   = v.x + b1[gn]   + b2[gn];
            crow[c*2+1] = v.y + b1[gn+1] + b2[gn+1];
        }
    }
}

// ---------------- one recurrent step, both directions of one layer ----------------
// grid 128 blocks: dir = blk>>6, 8 h-columns per block (64x32 gate tile incl. all 4 gates),
// fused LSTM elementwise. h is double-buffered by step parity (read s&1, write (s&1)^1).
__global__ __launch_bounds__(128) void lstm_step(const float* __restrict__ Whhf,
        const float* __restrict__ Whhb, int layer, int s)
{
    __shared__ __align__(16) float As[16][128];  // duplicated h tile
    __shared__ __align__(16) float Ws[16][32];
    __shared__ float gate_s[64*32];

    int tid = threadIdx.x;
    int dir = blockIdx.x >> 6;
    int chunk = blockIdx.x & 63;
    int n0 = chunk * 8;
    int t = dir ? (Tt - 1 - s) : s;
    int seq = layer * 2 + dir;

    const float* __restrict__ hprev = g_hbuf[seq][s & 1];
    float* __restrict__ hnext       = g_hbuf[seq][(s & 1) ^ 1];
    float* __restrict__ cst         = g_cbuf[seq];
    const float* __restrict__ Gb    = g_G + (size_t)seq * GSZ + (size_t)t * Bb * G4H;
    const float* __restrict__ Whh   = dir ? Whhb : Whhf;

    int ty = tid >> 3, tx = tid & 7;
    int mloc = ty * 4;       // 4 batch rows
    int cloc = tx * 4;       // 4 gate cols (within 32-col tile)

    // A-tile load mapping: idx = row*4 + k4, thread loads idx=tid and tid+128
    int a_row0 = tid >> 2,          a_k0 = tid & 3;
    int a_row1 = (tid + 128) >> 2;  // a_k1 == a_k0
    // W-tile: c = tid>>2 (0..31), k4 = tid&3; global row j = (c>>3)*512 + n0 + (c&7)
    int wc = tid >> 2, wk = tid & 3;
    int wj = ((wc >> 3) << 9) + n0 + (wc & 7);

    u64 acc[4][2];
#pragma unroll
    for (int r = 0; r < 4; r++) { acc[r][0] = 0ull; acc[r][1] = 0ull; }

    for (int k0 = 0; k0 < Hh; k0 += 16) {
        float4 av0 = *(const float4*)(hprev + a_row0 * Hh + k0 + a_k0 * 4);
        float4 av1 = *(const float4*)(hprev + a_row1 * Hh + k0 + a_k0 * 4);
        float4 wv  = *(const float4*)(Whh + (size_t)wj * Hh + k0 + wk * 4);
        __syncthreads();
        As[a_k0*4+0][2*a_row0] = av0.x; As[a_k0*4+0][2*a_row0+1] = av0.x;
        As[a_k0*4+1][2*a_row0] = av0.y; As[a_k0*4+1][2*a_row0+1] = av0.y;
        As[a_k0*4+2][2*a_row0] = av0.z; As[a_k0*4+2][2*a_row0+1] = av0.z;
        As[a_k0*4+3][2*a_row0] = av0.w; As[a_k0*4+3][2*a_row0+1] = av0.w;
        As[a_k0*4+0][2*a_row1] = av1.x; As[a_k0*4+0][2*a_row1+1] = av1.x;
        As[a_k0*4+1][2*a_row1] = av1.y; As[a_k0*4+1][2*a_row1+1] = av1.y;
        As[a_k0*4+2][2*a_row1] = av1.z; As[a_k0*4+2][2*a_row1+1] = av1.z;
        As[a_k0*4+3][2*a_row1] = av1.w; As[a_k0*4+3][2*a_row1+1] = av1.w;
        Ws[wk*4+0][wc] = wv.x;
        Ws[wk*4+1][wc] = wv.y;
        Ws[wk*4+2][wc] = wv.z;
        Ws[wk*4+3][wc] = wv.w;
        __syncthreads();
#pragma unroll
        for (int k = 0; k < 16; k++) {
            ulonglong2 a0 = *(const ulonglong2*)&As[k][2*mloc];
            ulonglong2 a1 = *(const ulonglong2*)&As[k][2*mloc+4];
            ulonglong2 bq = *(const ulonglong2*)&Ws[k][cloc];
            u64 ar[4] = {a0.x, a0.y, a1.x, a1.y};
#pragma unroll
            for (int r = 0; r < 4; r++) {
                fma2(acc[r][0], ar[r], bq.x);
                fma2(acc[r][1], ar[r], bq.y);
            }
        }
    }

    // epilogue: add precomputed input projection + biases, stage gates in smem
#pragma unroll
    for (int r = 0; r < 4; r++) {
        int m = mloc + r;
#pragma unroll
        for (int cp = 0; cp < 2; cp++) {
            float2 v = unpack2(acc[r][cp]);
            int cc = cloc + cp * 2;
            int j0 = ((cc >> 3) << 9) + n0 + (cc & 7);
            gate_s[m * 32 + cc]     = v.x + Gb[m * G4H + j0];
            gate_s[m * 32 + cc + 1] = v.y + Gb[m * G4H + j0 + 1];
        }
    }
    __syncthreads();

    // fused LSTM elementwise on this block's 64x8 (b,n) patch
    for (int p = tid; p < 512; p += 128) {
        int m = p >> 3, u = p & 7;
        float gi = gate_s[m*32 + u];
        float gf = gate_s[m*32 + 8 + u];
        float gg = gate_s[m*32 + 16 + u];
        float go = gate_s[m*32 + 24 + u];
        float i_s = sigm(gi);
        float f_s = sigm(gf);
        float g_t = tanhf(gg);
        float o_s = sigm(go);
        int ci = m * Hh + n0 + u;
        float cn = f_s * cst[ci] + i_s * g_t;
        float hn = o_s * tanhf(cn);
        cst[ci] = cn;
        hnext[ci] = hn;
        if (layer == 0)
            g_x1[(size_t)(t * Bb + m) * (2*Hh) + dir * Hh + n0 + u] = hn;
    }
}

// ---------------- output head: logits + log_softmax ----------------
__global__ void logits_kernel(const float* __restrict__ Wout,
                              const float* __restrict__ bout,
                              float* __restrict__ out)
{
    __shared__ float h[2048];
    __shared__ float red[256];
    __shared__ float lg[32];
    int b = blockIdx.x, tid = threadIdx.x;
    for (int i = tid; i < 2048; i += 256) {
        int seg = i >> 9, k = i & 511;           // order: l0f, l0b, l1f, l1b
        h[i] = g_hbuf[seg][0][b * Hh + k];       // final h lives in parity-0 buffer
    }
    __syncthreads();
    int e = tid >> 3, part = tid & 7;
    const float4* wrow = (const float4*)(Wout + (size_t)e * 2048 + part * 256);
    const float4* hp   = (const float4*)(h + part * 256);
    float sum = 0.f;
#pragma unroll 8
    for (int i = 0; i < 64; i++) {
        float4 wv = wrow[i], hv = hp[i];
        sum += wv.x*hv.x + wv.y*hv.y + wv.z*hv.z + wv.w*hv.w;
    }
    red[tid] = sum;
    __syncthreads();
    if (part == 0) {
        float s = 0.f;
#pragma unroll
        for (int i = 0; i < 8; i++) s += red[tid + i];
        lg[e] = s + bout[e];
    }
    __syncthreads();
    if (tid < 32) {
        float v = lg[tid];
        float mx = v;
#pragma unroll
        for (int off = 16; off > 0; off >>= 1)
            mx = fmaxf(mx, __shfl_xor_sync(0xffffffffu, mx, off));
        float ex = __expf(v - mx);
        float se = ex;
#pragma unroll
        for (int off = 16; off > 0; off >>= 1)
            se += __shfl_xor_sync(0xffffffffu, se, off);
        out[b * 32 + tid] = v - mx - logf(se);
    }
}

// ---------------- launch ----------------
extern "C" void kernel_launch(void* const* d_in, const int* in_sizes, int n_in,
                              void* d_out, int out_size)
{
    const int*   queries = (const int*)  d_in[0];
    const float* emb     = (const float*)d_in[1];
    const float* Wih0f = (const float*)d_in[2],  *Whh0f = (const float*)d_in[3];
    const float* bih0f = (const float*)d_in[4],  *bhh0f = (const float*)d_in[5];
    const float* Wih0b = (const float*)d_in[6],  *Whh0b = (const float*)d_in[7];
    const float* bih0b = (const float*)d_in[8],  *bhh0b = (const float*)d_in[9];
    const float* Wih1f = (const float*)d_in[10], *Whh1f = (const float*)d_in[11];
    const float* bih1f = (const float*)d_in[12], *bhh1f = (const float*)d_in[13];
    const float* Wih1b = (const float*)d_in[14], *Whh1b = (const float*)d_in[15];
    const float* bih1b = (const float*)d_in[16], *bhh1b = (const float*)d_in[17];
    const float* W_out = (const float*)d_in[18], *b_out = (const float*)d_in[19];

    init_states<<<1024, 256>>>();
    gather_embed<<<Tt*Bb, 64>>>(queries, emb);

    dim3 gg(G4H/128, (Tt*Bb)/128);   // (16, 64)
    sgemm_ff<<<gg, 256>>>(0, 0, Ee,   Wih0f, bih0f, bhh0f);
    sgemm_ff<<<gg, 256>>>(0, 1, Ee,   Wih0b, bih0b, bhh0b);

    for (int s = 0; s < Tt; s++)
        lstm_step<<<128, 128>>>(Whh0f, Whh0b, 0, s);

    sgemm_ff<<<gg, 256>>>(1, 2, 2*Hh, Wih1f, bih1f, bhh1f);
    sgemm_ff<<<gg, 256>>>(1, 3, 2*Hh, Wih1b, bih1b, bhh1b);

    for (int s = 0; s < Tt; s++)
        lstm_step<<<128, 128>>>(Whh1f, Whh1b, 1, s);

    logits_kernel<<<Bb, 256>>>(W_out, b_out, (float*)d_out);
}

// round 2
// speedup vs baseline: 1.6337x; 1.6337x over previous
#include <cuda_runtime.h>

#define Bb   64
#define Tt   128
#define Ee   256
#define Hh   512
#define G4H  2048
#define GSZ  (Tt*Bb*G4H)   /* 16,777,216 floats per gate buffer */

typedef unsigned long long u64;

// ---------------- scratch (__device__ globals: allocation-free) ----------------
__device__ float g_x0[Tt*Bb*Ee];                 // embedded inputs  [T*B, E]
__device__ float g_x1[Tt*Bb*2*Hh];               // layer-0 outputs  [T*B, 2H]
__device__ float g_G[(size_t)4*GSZ];             // gate pre-acts: G0f,G0b,G1f,G1b (256 MB)
__device__ float g_hT[4][Hh*Bb];                 // h transposed [k][b] per sequence
__device__ float g_c[4][Bb*Hh];                  // c state per sequence
__device__ float g_part[2][8*Bb*G4H];            // K-split partial gates per dir (4 MB each)
__device__ unsigned g_bar[2][2];                 // [layer][dir] barrier counters

// ---------------- packed f32x2 helpers ----------------
__device__ __forceinline__ void fma2(u64 &c, u64 a, u64 b) {
    asm("fma.rn.f32x2 %0, %1, %2, %0;" : "+l"(c) : "l"(a), "l"(b));
}
__device__ __forceinline__ float2 unpack2(u64 v) {
    float2 r; asm("mov.b64 {%0,%1}, %2;" : "=f"(r.x), "=f"(r.y) : "l"(v)); return r;
}
__device__ __forceinline__ u64 dup2(float v) {
    u64 r; asm("mov.b64 %0, {%1, %1};" : "=l"(r) : "f"(v)); return r;
}
__device__ __forceinline__ float sigm(float x) { return 1.f / (1.f + __expf(-x)); }

// ---------------- init: zero h, c, barriers ----------------
__global__ void init_states() {
    int i = blockIdx.x * blockDim.x + threadIdx.x;
    if (i < 4*Hh*Bb) ((float*)g_hT)[i] = 0.f;
    if (i < 4*Bb*Hh) ((float*)g_c)[i] = 0.f;
    if (i < 4)       ((unsigned*)g_bar)[i] = 0u;
}

// ---------------- embedding gather ----------------
__global__ void gather_embed(const int* __restrict__ q, const float* __restrict__ emb) {
    int r = blockIdx.x;              // r = t*B + b
    int b = r & (Bb - 1);
    int t = r >> 6;
    int qi = q[b * Tt + t];
    const float4* src = (const float4*)(emb + (size_t)qi * Ee);
    float4* dst = (float4*)(g_x0 + (size_t)r * Ee);
    dst[threadIdx.x] = src[threadIdx.x];
}

// ---------------- feedforward GEMM: C = A[8192,K] @ W[2048,K]^T + b1 + b2 ----------------
__global__ __launch_bounds__(256) void sgemm_ff(int asel, int gsel, int K,
        const float* __restrict__ W,
        const float* __restrict__ b1, const float* __restrict__ b2)
{
    const float* __restrict__ A = asel ? g_x1 : g_x0;
    float* __restrict__ C = g_G + (size_t)gsel * GSZ;

    __shared__ __align__(16) float As[8][256];   // duplicated A
    __shared__ __align__(16) float Bs[8][128];

    int tid = threadIdx.x;
    int m0 = blockIdx.y * 128;
    int n0 = blockIdx.x * 128;
    int ty = tid >> 4, tx = tid & 15;
    int mloc = ty * 8, nloc = tx * 8;

    u64 acc[8][4];
#pragma unroll
    for (int r = 0; r < 8; r++)
#pragma unroll
        for (int c = 0; c < 4; c++) acc[r][c] = 0ull;

    int lrow = tid >> 1;
    int lk = (tid & 1) * 4;
    const float* Ap = A + (size_t)(m0 + lrow) * K + lk;
    const float* Wp = W + (size_t)(n0 + lrow) * K + lk;

    for (int k0 = 0; k0 < K; k0 += 8) {
        float4 av = *(const float4*)(Ap + k0);
        float4 wv = *(const float4*)(Wp + k0);
        __syncthreads();
        As[lk+0][2*lrow] = av.x; As[lk+0][2*lrow+1] = av.x;
        As[lk+1][2*lrow] = av.y; As[lk+1][2*lrow+1] = av.y;
        As[lk+2][2*lrow] = av.z; As[lk+2][2*lrow+1] = av.z;
        As[lk+3][2*lrow] = av.w; As[lk+3][2*lrow+1] = av.w;
        Bs[lk+0][lrow] = wv.x;
        Bs[lk+1][lrow] = wv.y;
        Bs[lk+2][lrow] = wv.z;
        Bs[lk+3][lrow] = wv.w;
        __syncthreads();
#pragma unroll
        for (int k = 0; k < 8; k++) {
            ulonglong2 a0 = *(const ulonglong2*)&As[k][2*mloc];
            ulonglong2 a1 = *(const ulonglong2*)&As[k][2*mloc+4];
            ulonglong2 a2 = *(const ulonglong2*)&As[k][2*mloc+8];
            ulonglong2 a3 = *(const ulonglong2*)&As[k][2*mloc+12];
            ulonglong2 q0 = *(const ulonglong2*)&Bs[k][nloc];
            ulonglong2 q1 = *(const ulonglong2*)&Bs[k][nloc+4];
            u64 ar[8] = {a0.x,a0.y,a1.x,a1.y,a2.x,a2.y,a3.x,a3.y};
            u64 br[4] = {q0.x,q0.y,q1.x,q1.y};
#pragma unroll
            for (int r = 0; r < 8; r++)
#pragma unroll
                for (int c = 0; c < 4; c++)
                    fma2(acc[r][c], ar[r], br[c]);
        }
    }

#pragma unroll
    for (int r = 0; r < 8; r++) {
        int gm = m0 + mloc + r;
        float* crow = C + (size_t)gm * G4H + n0 + nloc;
#pragma unroll
        for (int c = 0; c < 4; c++) {
            float2 v = unpack2(acc[r][c]);
            int gn = n0 + nloc + c * 2;
            crow[c*2]   = v.x + b1[gn]   + b2[gn];
            crow[c*2+1] = v.y + b1[gn+1] + b2[gn+1];
        }
    }
}

// ---------------- per-direction software barrier (all blocks co-resident) ----------------
__device__ __forceinline__ void dirbar(unsigned* ctr, unsigned target) {
    __threadfence();                 // release: make this block's stores L2-visible
    __syncthreads();
    if (threadIdx.x == 0) {
        atomicAdd(ctr, 1u);
        unsigned v;
        do {
            asm volatile("ld.volatile.global.u32 %0, [%1];" : "=r"(v) : "l"(ctr));
            if (v >= target) break;
            __nanosleep(64);
        } while (true);
    }
    __syncthreads();
}

// ---------------- persistent recurrence: one layer, both dirs, 128 steps ----------------
// Grid 128 blocks x 256 thr. dir = blk>>6. Per dir, 64 blocks = 8 N-chunks(256) x 8 K-chunks(64).
// Phase A: K-split partial gate GEMM -> g_part. Barrier. Phase B: deterministic partial
// reduction + precomputed input proj + fused LSTM elementwise -> hT. Barrier.
__global__ __launch_bounds__(256) void lstm_persist(
        const float* __restrict__ Whhf, const float* __restrict__ Whhb, int layer)
{
    __shared__ __align__(16) float As[8][128];   // duplicated h tile (8k x 64m dup)
    __shared__ __align__(16) float Bs[8][256];   // Whh tile

    const int tid = threadIdx.x;
    const int dir = blockIdx.x >> 6;
    const int sub = blockIdx.x & 63;
    const int nc  = sub & 7;      // N chunk: cols nc*256..+255
    const int kc  = sub >> 3;     // K chunk: ks  kc*64..+63
    const int seq = layer * 2 + dir;

    const float* __restrict__ Whh = dir ? Whhb : Whhf;
    float* __restrict__ hT = g_hT[seq];
    float* __restrict__ cs = g_c[seq];
    float* __restrict__ Pp = g_part[dir];
    const float* __restrict__ Gseq = g_G + (size_t)seq * GSZ;
    unsigned* bar = &g_bar[layer][dir];

    const int ty = tid >> 5, tx = tid & 31;
    const int mloc = ty * 8, nloc = tx * 8;
    const int a_k = tid >> 4, a_m = (tid & 15) * 4;     // A staging (tid<128)
    const float* Wrow = Whh + (size_t)(nc*256 + tid) * Hh + kc*64;

    const int n0  = sub * 8;                  // elementwise h-col slice
    const int m_e = tid >> 3, u_e = tid & 7;  // elementwise elems (m_e,u), (m_e+32,u)

    for (int s = 0; s < Tt; s++) {
        const int t = dir ? (Tt - 1 - s) : s;

        // ---------- phase A: partial gate GEMM over this K chunk ----------
        u64 acc[8][4];
#pragma unroll
        for (int r = 0; r < 8; r++) { acc[r][0]=0; acc[r][1]=0; acc[r][2]=0; acc[r][3]=0; }

        for (int k0 = 0; k0 < 64; k0 += 8) {
            float4 av;
            if (tid < 128)
                av = __ldcg((const float4*)(hT + (kc*64 + k0 + a_k) * Bb + a_m));
            float4 wv  = *(const float4*)(Wrow + k0);
            float4 wv2 = *(const float4*)(Wrow + k0 + 4);
            __syncthreads();
            if (tid < 128) {
                *(u64*)&As[a_k][2*a_m]     = dup2(av.x);
                *(u64*)&As[a_k][2*a_m + 2] = dup2(av.y);
                *(u64*)&As[a_k][2*a_m + 4] = dup2(av.z);
                *(u64*)&As[a_k][2*a_m + 6] = dup2(av.w);
            }
            Bs[0][tid] = wv.x;  Bs[1][tid] = wv.y;  Bs[2][tid] = wv.z;  Bs[3][tid] = wv.w;
            Bs[4][tid] = wv2.x; Bs[5][tid] = wv2.y; Bs[6][tid] = wv2.z; Bs[7][tid] = wv2.w;
            __syncthreads();
#pragma unroll
            for (int k = 0; k < 8; k++) {
                ulonglong2 a0 = *(const ulonglong2*)&As[k][2*mloc];
                ulonglong2 a1 = *(const ulonglong2*)&As[k][2*mloc+4];
                ulonglong2 a2 = *(const ulonglong2*)&As[k][2*mloc+8];
                ulonglong2 a3 = *(const ulonglong2*)&As[k][2*mloc+12];
                ulonglong2 q0 = *(const ulonglong2*)&Bs[k][nloc];
                ulonglong2 q1 = *(const ulonglong2*)&Bs[k][nloc+4];
                u64 ar[8] = {a0.x,a0.y,a1.x,a1.y,a2.x,a2.y,a3.x,a3.y};
                u64 br[4] = {q0.x,q0.y,q1.x,q1.y};
#pragma unroll
                for (int r = 0; r < 8; r++)
#pragma unroll
                    for (int c = 0; c < 4; c++)
                        fma2(acc[r][c], ar[r], br[c]);
            }
        }
        // store 64x256 partial slab (f32x2 acc bit layout == float2)
#pragma unroll
        for (int r = 0; r < 8; r++) {
            float* prow = Pp + (size_t)(kc*Bb + mloc + r) * G4H + nc*256 + nloc;
            ulonglong2 v0; v0.x = acc[r][0]; v0.y = acc[r][1];
            ulonglong2 v1; v1.x = acc[r][2]; v1.y = acc[r][3];
            *(ulonglong2*)prow       = v0;
            *(ulonglong2*)(prow + 4) = v1;
        }

        dirbar(bar, 64u * (2*s + 1));

        // ---------- phase B: reduce partials + fused LSTM elementwise ----------
        const float* Gt = Gseq + (size_t)t * Bb * G4H;
#pragma unroll
        for (int e = 0; e < 2; e++) {
            int m = m_e + e * 32;
            float pre[4];
#pragma unroll
            for (int g = 0; g < 4; g++) {
                int col = g * Hh + n0 + u_e;
                float v = Gt[(size_t)m * G4H + col];
#pragma unroll
                for (int q = 0; q < 8; q++)
                    v += __ldcg(&Pp[(size_t)(q*Bb + m) * G4H + col]);
                pre[g] = v;
            }
            float i_s = sigm(pre[0]);
            float f_s = sigm(pre[1]);
            float g_t = tanhf(pre[2]);
            float o_s = sigm(pre[3]);
            int ci = m * Hh + n0 + u_e;
            float cn = f_s * cs[ci] + i_s * g_t;
            float hn = o_s * tanhf(cn);
            cs[ci] = cn;
            hT[(n0 + u_e) * Bb + m] = hn;
            if (layer == 0)
                g_x1[((size_t)t * Bb + m) * (2*Hh) + dir * Hh + n0 + u_e] = hn;
        }

        dirbar(bar, 64u * (2*s + 2));
    }
}

// ---------------- output head: logits + log_softmax ----------------
__global__ void logits_kernel(const float* __restrict__ Wout,
                              const float* __restrict__ bout,
                              float* __restrict__ out)
{
    __shared__ float h[2048];
    __shared__ float red[256];
    __shared__ float lg[32];
    int b = blockIdx.x, tid = threadIdx.x;
    for (int i = tid; i < 2048; i += 256) {
        int seg = i >> 9, k = i & 511;           // order: l0f, l0b, l1f, l1b
        h[i] = g_hT[seg][k * Bb + b];
    }
    __syncthreads();
    int e = tid >> 3, part = tid & 7;
    const float4* wrow = (const float4*)(Wout + (size_t)e * 2048 + part * 256);
    const float4* hp   = (const float4*)(h + part * 256);
    float sum = 0.f;
#pragma unroll 8
    for (int i = 0; i < 64; i++) {
        float4 wv = wrow[i], hv = hp[i];
        sum += wv.x*hv.x + wv.y*hv.y + wv.z*hv.z + wv.w*hv.w;
    }
    red[tid] = sum;
    __syncthreads();
    if (part == 0) {
        float sacc = 0.f;
#pragma unroll
        for (int i = 0; i < 8; i++) sacc += red[tid + i];
        lg[e] = sacc + bout[e];
    }
    __syncthreads();
    if (tid < 32) {
        float v = lg[tid];
        float mx = v;
#pragma unroll
        for (int off = 16; off > 0; off >>= 1)
            mx = fmaxf(mx, __shfl_xor_sync(0xffffffffu, mx, off));
        float ex = __expf(v - mx);
        float se = ex;
#pragma unroll
        for (int off = 16; off > 0; off >>= 1)
            se += __shfl_xor_sync(0xffffffffu, se, off);
        out[b * 32 + tid] = v - mx - logf(se);
    }
}

// ---------------- launch ----------------
extern "C" void kernel_launch(void* const* d_in, const int* in_sizes, int n_in,
                              void* d_out, int out_size)
{
    const int*   queries = (const int*)  d_in[0];
    const float* emb     = (const float*)d_in[1];
    const float* Wih0f = (const float*)d_in[2],  *Whh0f = (const float*)d_in[3];
    const float* bih0f = (const float*)d_in[4],  *bhh0f = (const float*)d_in[5];
    const float* Wih0b = (const float*)d_in[6],  *Whh0b = (const float*)d_in[7];
    const float* bih0b = (const float*)d_in[8],  *bhh0b = (const float*)d_in[9];
    const float* Wih1f = (const float*)d_in[10], *Whh1f = (const float*)d_in[11];
    const float* bih1f = (const float*)d_in[12], *bhh1f = (const float*)d_in[13];
    const float* Wih1b = (const float*)d_in[14], *Whh1b = (const float*)d_in[15];
    const float* bih1b = (const float*)d_in[16], *bhh1b = (const float*)d_in[17];
    const float* W_out = (const float*)d_in[18], *b_out = (const float*)d_in[19];

    init_states<<<512, 256>>>();
    gather_embed<<<Tt*Bb, 64>>>(queries, emb);

    dim3 gg(G4H/128, (Tt*Bb)/128);   // (16, 64)
    sgemm_ff<<<gg, 256>>>(0, 0, Ee,   Wih0f, bih0f, bhh0f);
    sgemm_ff<<<gg, 256>>>(0, 1, Ee,   Wih0b, bih0b, bhh0b);

    lstm_persist<<<128, 256>>>(Whh0f, Whh0b, 0);

    sgemm_ff<<<gg, 256>>>(1, 2, 2*Hh, Wih1f, bih1f, bhh1f);
    sgemm_ff<<<gg, 256>>>(1, 3, 2*Hh, Wih1b, bih1b, bhh1b);

    lstm_persist<<<128, 256>>>(Whh1f, Whh1b, 1);

    logits_kernel<<<Bb, 256>>>(W_out, b_out, (float*)d_out);
}

// round 4
// speedup vs baseline: 1.8250x; 1.1171x over previous
#include <cuda_runtime.h>

#define Bb   64
#define Tt   128
#define Ee   256
#define Hh   512
#define G4H  2048
#define GSZ  (Tt*Bb*G4H)   /* 16,777,216 floats per gate buffer */
#define PSTRIDE 34         /* padded col stride of pslab to break bank conflicts */

typedef unsigned long long u64;

// ---------------- scratch (__device__ globals: allocation-free) ----------------
__device__ float g_x0[Tt*Bb*Ee];                 // embedded inputs  [T*B, E]
__device__ float g_x1[Tt*Bb*2*Hh];               // layer-0 outputs  [T*B, 2H]
__device__ float g_G[(size_t)4*GSZ];             // gate pre-acts: G0f,G0b,G1f,G1b
__device__ float g_WT[4][Hh*G4H];                // Whh transposed [k][j] per sequence
__device__ float g_hT[4][Hh*Bb];                 // h transposed [k][b] per sequence
__device__ float g_c[4][Bb*Hh];                  // c state per sequence
__device__ unsigned g_bar[2][2];                 // [layer][dir] barrier counters

// ---------------- packed f32x2 helpers ----------------
__device__ __forceinline__ void fma2(u64 &c, u64 a, u64 b) {
    asm("fma.rn.f32x2 %0, %1, %2, %0;" : "+l"(c) : "l"(a), "l"(b));
}
__device__ __forceinline__ u64 dup2(float v) {
    u64 r; asm("mov.b64 %0, {%1, %1};" : "=l"(r) : "f"(v)); return r;
}
__device__ __forceinline__ float2 unpack2(u64 v) {
    float2 r; asm("mov.b64 {%0,%1}, %2;" : "=f"(r.x), "=f"(r.y) : "l"(v)); return r;
}
__device__ __forceinline__ float sigm(float x) { return 1.f / (1.f + __expf(-x)); }

// ---------------- init: zero h, c, barriers ----------------
__global__ void init_states() {
    int i = blockIdx.x * blockDim.x + threadIdx.x;
    if (i < 4*Hh*Bb) ((float*)g_hT)[i] = 0.f;
    if (i < 4*Bb*Hh) ((float*)g_c)[i] = 0.f;
    if (i < 4)       ((unsigned*)g_bar)[i] = 0u;
}

// ---------------- Whh transpose: g_WT[seq][k*2048+j] = Whh[j*512+k] ----------------
__global__ void transposeW(const float* __restrict__ W, int seq) {
    __shared__ float tile[32][33];
    int j0 = blockIdx.x * 32, k0 = blockIdx.y * 32;
    int tx = threadIdx.x, ty = threadIdx.y;
#pragma unroll
    for (int r = 0; r < 32; r += 8)
        tile[ty + r][tx] = W[(size_t)(j0 + ty + r) * Hh + k0 + tx];
    __syncthreads();
    float* WT = g_WT[seq];
#pragma unroll
    for (int r = 0; r < 32; r += 8)
        WT[(size_t)(k0 + ty + r) * G4H + j0 + tx] = tile[tx][ty + r];
}

// ---------------- embedding gather ----------------
__global__ void gather_embed(const int* __restrict__ q, const float* __restrict__ emb) {
    int r = blockIdx.x;              // r = t*B + b
    int b = r & (Bb - 1);
    int t = r >> 6;
    int qi = q[b * Tt + t];
    const float4* src = (const float4*)(emb + (size_t)qi * Ee);
    float4* dst = (float4*)(g_x0 + (size_t)r * Ee);
    dst[threadIdx.x] = src[threadIdx.x];
}

// ---------------- feedforward GEMM: C = A[8192,K] @ W[2048,K]^T + b1 + b2 ----------------
__global__ __launch_bounds__(256) void sgemm_ff(int asel, int gsel, int K,
        const float* __restrict__ W,
        const float* __restrict__ b1, const float* __restrict__ b2)
{
    const float* __restrict__ A = asel ? g_x1 : g_x0;
    float* __restrict__ C = g_G + (size_t)gsel * GSZ;

    __shared__ __align__(16) float As[8][256];   // duplicated A
    __shared__ __align__(16) float Bs[8][128];

    int tid = threadIdx.x;
    int m0 = blockIdx.y * 128;
    int n0 = blockIdx.x * 128;
    int ty = tid >> 4, tx = tid & 15;
    int mloc = ty * 8, nloc = tx * 8;

    u64 acc[8][4];
#pragma unroll
    for (int r = 0; r < 8; r++)
#pragma unroll
        for (int c = 0; c < 4; c++) acc[r][c] = 0ull;

    int lrow = tid >> 1;
    int lk = (tid & 1) * 4;
    const float* Ap = A + (size_t)(m0 + lrow) * K + lk;
    const float* Wp = W + (size_t)(n0 + lrow) * K + lk;

    for (int k0 = 0; k0 < K; k0 += 8) {
        float4 av = *(const float4*)(Ap + k0);
        float4 wv = *(const float4*)(Wp + k0);
        __syncthreads();
        As[lk+0][2*lrow] = av.x; As[lk+0][2*lrow+1] = av.x;
        As[lk+1][2*lrow] = av.y; As[lk+1][2*lrow+1] = av.y;
        As[lk+2][2*lrow] = av.z; As[lk+2][2*lrow+1] = av.z;
        As[lk+3][2*lrow] = av.w; As[lk+3][2*lrow+1] = av.w;
        Bs[lk+0][lrow] = wv.x;
        Bs[lk+1][lrow] = wv.y;
        Bs[lk+2][lrow] = wv.z;
        Bs[lk+3][lrow] = wv.w;
        __syncthreads();
#pragma unroll
        for (int k = 0; k < 8; k++) {
            ulonglong2 a0 = *(const ulonglong2*)&As[k][2*mloc];
            ulonglong2 a1 = *(const ulonglong2*)&As[k][2*mloc+4];
            ulonglong2 a2 = *(const ulonglong2*)&As[k][2*mloc+8];
            ulonglong2 a3 = *(const ulonglong2*)&As[k][2*mloc+12];
            ulonglong2 q0 = *(const ulonglong2*)&Bs[k][nloc];
            ulonglong2 q1 = *(const ulonglong2*)&Bs[k][nloc+4];
            u64 ar[8] = {a0.x,a0.y,a1.x,a1.y,a2.x,a2.y,a3.x,a3.y};
            u64 br[4] = {q0.x,q0.y,q1.x,q1.y};
#pragma unroll
            for (int r = 0; r < 8; r++)
#pragma unroll
                for (int c = 0; c < 4; c++)
                    fma2(acc[r][c], ar[r], br[c]);
        }
    }

#pragma unroll
    for (int r = 0; r < 8; r++) {
        int gm = m0 + mloc + r;
        float* crow = C + (size_t)gm * G4H + n0 + nloc;
#pragma unroll
        for (int c = 0; c < 4; c++) {
            float2 v = unpack2(acc[r][c]);
            int gn = n0 + nloc + c * 2;
            crow[c*2]   = v.x + b1[gn]   + b2[gn];
            crow[c*2+1] = v.y + b1[gn+1] + b2[gn+1];
        }
    }
}

// ---------------- per-direction software barrier (all blocks co-resident) ----------------
__device__ __forceinline__ void dirbar(unsigned* ctr, unsigned target) {
    __threadfence();                 // release: make this block's stores L2-visible
    __syncthreads();
    if (threadIdx.x == 0) {
        atomicAdd(ctr, 1u);
        unsigned v;
        do {
            asm volatile("ld.volatile.global.u32 %0, [%1];" : "=r"(v) : "l"(ctr));
            if (v >= target) break;
            __nanosleep(64);
        } while (true);
    }
    __syncthreads();
}

// ---------------- persistent recurrence: one layer, both dirs, 128 steps ----------------
// 128 blocks x 256 thr. dir = blk>>6, sub = blk&63 -> 8 h-cols (gate cols g*512+sub*8+u).
// Warp w handles K-slice [w*64, w*64+64); lane microtile 8m x 8c (4 col-pairs, f32x2).
// Two-round in-block K-reduction through a 4-slab smem buffer (fits static 48KB),
// fused LSTM elementwise, ONE global barrier per step.
#define LOAD_A(buf, kb) { \
    _Pragma("unroll") for (int kk = 0; kk < 4; kk++) { \
        const float4* p = (const float4*)(hT + ((kb) + kk) * Bb + m0); \
        buf[kk][0] = __ldcg(p); buf[kk][1] = __ldcg(p + 1); } }

#define COMPUTE(buf, kb) { \
    _Pragma("unroll") for (int kk = 0; kk < 4; kk++) { \
        const ulonglong2* bp = (const ulonglong2*)(WT + (size_t)((kb) + kk) * G4H + cb); \
        ulonglong2 b0 = bp[0], b1 = bp[1]; \
        u64 br0 = b0.x, br1 = b0.y, br2 = b1.x, br3 = b1.y; \
        float av[8] = { buf[kk][0].x, buf[kk][0].y, buf[kk][0].z, buf[kk][0].w, \
                        buf[kk][1].x, buf[kk][1].y, buf[kk][1].z, buf[kk][1].w }; \
        _Pragma("unroll") for (int mi = 0; mi < 8; mi++) { \
            u64 ad = dup2(av[mi]); \
            fma2(acc[mi][0], ad, br0); fma2(acc[mi][1], ad, br1); \
            fma2(acc[mi][2], ad, br2); fma2(acc[mi][3], ad, br3); } } }

__global__ __launch_bounds__(256, 1) void lstm_persist(int layer)
{
    __shared__ float pslab[4 * Bb * PSTRIDE];    // 34,816 B static

    const int tid = threadIdx.x;
    const int dir = blockIdx.x >> 6;
    const int sub = blockIdx.x & 63;
    const int seq = layer * 2 + dir;
    const int w   = tid >> 5;
    const int lane = tid & 31;
    const int lane_m = lane >> 2;                // 0..7  -> m0 = lane_m*8
    const int lane_c = lane & 3;                 // 0..3  -> gate g
    const int m0 = lane_m * 8;
    const int cb = lane_c * Hh + sub * 8;        // global gate-col base (8 cols)
    const int ks = w * 64;
    const int wslab = w & 3;                     // slab index shared by w and w+4

    const float* __restrict__ WT = g_WT[seq];
    float* __restrict__ hT = g_hT[seq];
    float* __restrict__ cs = g_c[seq];
    const float* __restrict__ Gseq = g_G + (size_t)seq * GSZ;
    unsigned* bar = &g_bar[layer][dir];

    const int ew_m = tid >> 3, ew_u = tid & 7;   // elementwise: elems (ew_m,u) and (+32,u)

    for (int s = 0; s < Tt; s++) {
        const int t = dir ? (Tt - 1 - s) : s;

        // ---------- per-warp partial GEMM over its K slice (regs only) ----------
        u64 acc[8][4];
#pragma unroll
        for (int mi = 0; mi < 8; mi++) { acc[mi][0]=0; acc[mi][1]=0; acc[mi][2]=0; acc[mi][3]=0; }

        float4 A0[4][2], A1[4][2];
        LOAD_A(A0, ks);
#pragma unroll 1
        for (int kq = 0; kq < 64; kq += 8) {
            LOAD_A(A1, ks + kq + 4);
            COMPUTE(A0, ks + kq);
            if (kq + 8 < 64) LOAD_A(A0, ks + kq + 8);
            COMPUTE(A1, ks + kq + 4);
        }

        // ---------- round 1: warps 0-3 write slabs ----------
        if (w < 4) {
#pragma unroll
            for (int mi = 0; mi < 8; mi++) {
                float* prow = &pslab[(wslab * Bb + m0 + mi) * PSTRIDE + lane_c * 8];
                *(u64*)(prow)     = acc[mi][0];
                *(u64*)(prow + 2) = acc[mi][1];
                *(u64*)(prow + 4) = acc[mi][2];
                *(u64*)(prow + 6) = acc[mi][3];
            }
        }
        __syncthreads();
        // ---------- round 2: warps 4-7 accumulate into partner slab ----------
        if (w >= 4) {
#pragma unroll
            for (int mi = 0; mi < 8; mi++) {
                float* prow = &pslab[(wslab * Bb + m0 + mi) * PSTRIDE + lane_c * 8];
#pragma unroll
                for (int c = 0; c < 4; c++) {
                    float2 cur = *(float2*)(prow + 2*c);
                    float2 ad  = unpack2(acc[mi][c]);
                    cur.x += ad.x; cur.y += ad.y;
                    *(float2*)(prow + 2*c) = cur;
                }
            }
        }
        __syncthreads();

        // ---------- K-reduce (4 slabs) + input proj + fused LSTM elementwise ----------
        const float* Gt = Gseq + (size_t)t * Bb * G4H;
#pragma unroll
        for (int e = 0; e < 2; e++) {
            int m = ew_m + e * 32;
            float pre[4];
#pragma unroll
            for (int g = 0; g < 4; g++) {
                float v = Gt[(size_t)m * G4H + g * Hh + sub * 8 + ew_u];
#pragma unroll
                for (int ww = 0; ww < 4; ww++)
                    v += pslab[(ww * Bb + m) * PSTRIDE + g * 8 + ew_u];
                pre[g] = v;
            }
            float i_s = sigm(pre[0]);
            float f_s = sigm(pre[1]);
            float g_t = tanhf(pre[2]);
            float o_s = sigm(pre[3]);
            int ci = m * Hh + sub * 8 + ew_u;
            float cn = f_s * cs[ci] + i_s * g_t;
            float hn = o_s * tanhf(cn);
            cs[ci] = cn;
            hT[(sub * 8 + ew_u) * Bb + m] = hn;
            if (layer == 0)
                g_x1[((size_t)t * Bb + m) * (2*Hh) + dir * Hh + sub * 8 + ew_u] = hn;
        }

        dirbar(bar, 64u * (s + 1));   // single barrier: h complete for next step
    }
}

// ---------------- output head: logits + log_softmax ----------------
__global__ void logits_kernel(const float* __restrict__ Wout,
                              const float* __restrict__ bout,
                              float* __restrict__ out)
{
    __shared__ float h[2048];
    __shared__ float red[256];
    __shared__ float lg[32];
    int b = blockIdx.x, tid = threadIdx.x;
    for (int i = tid; i < 2048; i += 256) {
        int seg = i >> 9, k = i & 511;           // order: l0f, l0b, l1f, l1b
        h[i] = g_hT[seg][k * Bb + b];
    }
    __syncthreads();
    int e = tid >> 3, part = tid & 7;
    const float4* wrow = (const float4*)(Wout + (size_t)e * 2048 + part * 256);
    const float4* hp   = (const float4*)(h + part * 256);
    float sum = 0.f;
#pragma unroll 8
    for (int i = 0; i < 64; i++) {
        float4 wv = wrow[i], hv = hp[i];
        sum += wv.x*hv.x + wv.y*hv.y + wv.z*hv.z + wv.w*hv.w;
    }
    red[tid] = sum;
    __syncthreads();
    if (part == 0) {
        float sacc = 0.f;
#pragma unroll
        for (int i = 0; i < 8; i++) sacc += red[tid + i];
        lg[e] = sacc + bout[e];
    }
    __syncthreads();
    if (tid < 32) {
        float v = lg[tid];
        float mx = v;
#pragma unroll
        for (int off = 16; off > 0; off >>= 1)
            mx = fmaxf(mx, __shfl_xor_sync(0xffffffffu, mx, off));
        float ex = __expf(v - mx);
        float se = ex;
#pragma unroll
        for (int off = 16; off > 0; off >>= 1)
            se += __shfl_xor_sync(0xffffffffu, se, off);
        out[b * 32 + tid] = v - mx - logf(se);
    }
}

// ---------------- launch ----------------
extern "C" void kernel_launch(void* const* d_in, const int* in_sizes, int n_in,
                              void* d_out, int out_size)
{
    const int*   queries = (const int*)  d_in[0];
    const float* emb     = (const float*)d_in[1];
    const float* Wih0f = (const float*)d_in[2],  *Whh0f = (const float*)d_in[3];
    const float* bih0f = (const float*)d_in[4],  *bhh0f = (const float*)d_in[5];
    const float* Wih0b = (const float*)d_in[6],  *Whh0b = (const float*)d_in[7];
    const float* bih0b = (const float*)d_in[8],  *bhh0b = (const float*)d_in[9];
    const float* Wih1f = (const float*)d_in[10], *Whh1f = (const float*)d_in[11];
    const float* bih1f = (const float*)d_in[12], *bhh1f = (const float*)d_in[13];
    const float* Wih1b = (const float*)d_in[14], *Whh1b = (const float*)d_in[15];
    const float* bih1b = (const float*)d_in[16], *bhh1b = (const float*)d_in[17];
    const float* W_out = (const float*)d_in[18], *b_out = (const float*)d_in[19];

    init_states<<<512, 256>>>();
    gather_embed<<<Tt*Bb, 64>>>(queries, emb);

    dim3 tg(G4H/32, Hh/32);
    transposeW<<<tg, dim3(32,8)>>>(Whh0f, 0);
    transposeW<<<tg, dim3(32,8)>>>(Whh0b, 1);
    transposeW<<<tg, dim3(32,8)>>>(Whh1f, 2);
    transposeW<<<tg, dim3(32,8)>>>(Whh1b, 3);

    dim3 gg(G4H/128, (Tt*Bb)/128);   // (16, 64)
    sgemm_ff<<<gg, 256>>>(0, 0, Ee,   Wih0f, bih0f, bhh0f);
    sgemm_ff<<<gg, 256>>>(0, 1, Ee,   Wih0b, bih0b, bhh0b);

    lstm_persist<<<128, 256>>>(0);

    sgemm_ff<<<gg, 256>>>(1, 2, 2*Hh, Wih1f, bih1f, bhh1f);
    sgemm_ff<<<gg, 256>>>(1, 3, 2*Hh, Wih1b, bih1b, bhh1b);

    lstm_persist<<<128, 256>>>(1);

    logits_kernel<<<Bb, 256>>>(W_out, b_out, (float*)d_out);
}